// round 13
// baseline (speedup 1.0000x reference)
#include <cuda_runtime.h>
#include <math.h>
#include <stdint.h>

#define Bsz 32
#define N1 512
#define N2 256
#define Dd 256
#define Hh 8
#define HD 32
#define Ss 768
#define TWOD 512

typedef unsigned long long ull;

// ---------------- f32x2 packed-FMA helpers (sm_103a) ----------------
__device__ __forceinline__ ull pack2(float lo, float hi) {
    ull r; asm("mov.b64 %0, {%1, %2};" : "=l"(r) : "f"(lo), "f"(hi)); return r;
}
__device__ __forceinline__ void unpack2(ull v, float& lo, float& hi) {
    asm("mov.b64 {%0, %1}, %2;" : "=f"(lo), "=f"(hi) : "l"(v));
}
__device__ __forceinline__ void ffma2(ull& d, ull a, ull b) {
    asm("fma.rn.f32x2 %0, %1, %2, %0;" : "+l"(d) : "l"(a), "l"(b));
}
__device__ __forceinline__ ull mul2(ull a, ull b) {
    ull r; asm("mul.rn.f32x2 %0, %1, %2;" : "=l"(r) : "l"(a), "l"(b)); return r;
}
__device__ __forceinline__ ull add2(ull a, ull b) {
    ull r; asm("add.rn.f32x2 %0, %1, %2;" : "=l"(r) : "l"(a), "l"(b)); return r;
}

// ---------------- static scratch (no allocations allowed) ----------------
__device__ float g_m[Bsz * TWOD];
__device__ float g_w[Bsz * 4];
__device__ float g_lf[(size_t)Bsz * Ss * Dd];
__device__ float g_xout[(size_t)Bsz * N1 * Dd];
__device__ float g_xout2[(size_t)Bsz * N1 * Dd];
__device__ float g_qkv[(size_t)Bsz * Ss * 3 * Dd];
__device__ float g_oattn[(size_t)Bsz * Ss * Dd];

// ---------------- small kernels ----------------
__global__ void mean_kernel(const float* __restrict__ x1, const float* __restrict__ x2) {
    int b = blockIdx.x;
    int part = blockIdx.y;
    int d = threadIdx.x;
    if (part == 0) {
        const float* p = x1 + (size_t)b * N1 * Dd + d;
        float s = 0.f;
        for (int n = 0; n < N1; n++) s += p[(size_t)n * Dd];
        g_m[b * TWOD + d] = s * (1.0f / N1);
    } else {
        const float* p = x2 + (size_t)b * N2 * Dd + d;
        float s = 0.f;
        for (int n = 0; n < N2; n++) s += p[(size_t)n * Dd];
        g_m[b * TWOD + 256 + d] = s * (1.0f / N2);
    }
}

__global__ void router_kernel(const float* __restrict__ r_w1, const float* __restrict__ r_b1,
                              const float* __restrict__ ln_g, const float* __restrict__ ln_b,
                              const float* __restrict__ r_w2, const float* __restrict__ r_b2) {
    int b = blockIdx.x;
    int tid = threadIdx.x;
    __shared__ float ms[TWOD];
    __shared__ float red[256];
    __shared__ float hb[256];
    __shared__ float logits[4];
    ms[tid] = g_m[b * TWOD + tid];
    ms[tid + 256] = g_m[b * TWOD + 256 + tid];
    __syncthreads();
    float acc = r_b1[tid];
    const float* wr = r_w1 + (size_t)tid * TWOD;
    #pragma unroll 8
    for (int k = 0; k < TWOD; k++) acc = fmaf(ms[k], wr[k], acc);
    red[tid] = acc; __syncthreads();
    for (int s = 128; s > 0; s >>= 1) { if (tid < s) red[tid] += red[tid + s]; __syncthreads(); }
    float mu = red[0] * (1.0f / 256.0f); __syncthreads();
    float dv = acc - mu;
    red[tid] = dv * dv; __syncthreads();
    for (int s = 128; s > 0; s >>= 1) { if (tid < s) red[tid] += red[tid + s]; __syncthreads(); }
    float var = red[0] * (1.0f / 256.0f); __syncthreads();
    float xn = dv * rsqrtf(var + 1e-5f) * ln_g[tid] + ln_b[tid];
    float hv = 0.5f * xn * (1.0f + erff(xn * 0.70710678118654752f));
    hb[tid] = hv; __syncthreads();
    for (int e = 0; e < 4; e++) {
        red[tid] = hb[tid] * r_w2[e * 256 + tid]; __syncthreads();
        for (int s = 128; s > 0; s >>= 1) { if (tid < s) red[tid] += red[tid + s]; __syncthreads(); }
        if (tid == 0) logits[e] = red[0] + r_b2[e];
        __syncthreads();
    }
    if (tid == 0) {
        float mx = fmaxf(fmaxf(logits[0], logits[1]), fmaxf(logits[2], logits[3]));
        float e0 = expf(logits[0] - mx), e1 = expf(logits[1] - mx);
        float e2 = expf(logits[2] - mx), e3 = expf(logits[3] - mx);
        float inv = 1.0f / (e0 + e1 + e2 + e3);
        g_w[b * 4 + 0] = e0 * inv; g_w[b * 4 + 1] = e1 * inv;
        g_w[b * 4 + 2] = e2 * inv; g_w[b * 4 + 3] = e3 * inv;
    }
}

// ---------------- GEMM cores (R8-proven inner loop, runtime act) ----------------
#define BM 128
#define BN 128
#define BKt 16

__device__ __forceinline__ float act_elu(float v, int act) {
    return (act && v <= 0.f) ? expm1f(v) : v;
}

__device__ __forceinline__ void gemm_nt_core(const float* Ar0, const float* Ar1,
                                             const float* __restrict__ W,
                                             const float* __restrict__ bias,
                                             float* __restrict__ C,
                                             int mBase, int nBase, int N, int K, int act) {
    __shared__ float As[BKt][BM];
    __shared__ float Ws[BKt][BN];
    int tid = threadIdx.x;
    int tx = tid & 15, ty = tid >> 4;
    int lrow0 = tid >> 2, lc4 = (tid & 3) * 4;

    ull acc2[8][4];
    #pragma unroll
    for (int i = 0; i < 8; i++)
        #pragma unroll
        for (int j = 0; j < 4; j++) acc2[i][j] = 0ull;

    const float* Wr0 = W + (size_t)(nBase + lrow0) * K + lc4;
    const float* Wr1 = W + (size_t)(nBase + 64 + lrow0) * K + lc4;

    float4 sa0 = *(const float4*)Ar0;
    float4 sa1 = *(const float4*)Ar1;
    float4 sw0 = *(const float4*)Wr0;
    float4 sw1 = *(const float4*)Wr1;

    for (int k0 = 0; k0 < K; k0 += BKt) {
        As[lc4 + 0][lrow0] = sa0.x; As[lc4 + 1][lrow0] = sa0.y; As[lc4 + 2][lrow0] = sa0.z; As[lc4 + 3][lrow0] = sa0.w;
        As[lc4 + 0][64 + lrow0] = sa1.x; As[lc4 + 1][64 + lrow0] = sa1.y; As[lc4 + 2][64 + lrow0] = sa1.z; As[lc4 + 3][64 + lrow0] = sa1.w;
        Ws[lc4 + 0][lrow0] = sw0.x; Ws[lc4 + 1][lrow0] = sw0.y; Ws[lc4 + 2][lrow0] = sw0.z; Ws[lc4 + 3][lrow0] = sw0.w;
        Ws[lc4 + 0][64 + lrow0] = sw1.x; Ws[lc4 + 1][64 + lrow0] = sw1.y; Ws[lc4 + 2][64 + lrow0] = sw1.z; Ws[lc4 + 3][64 + lrow0] = sw1.w;
        __syncthreads();

        if (k0 + BKt < K) {
            int off = k0 + BKt;
            sa0 = *(const float4*)(Ar0 + off);
            sa1 = *(const float4*)(Ar1 + off);
            sw0 = *(const float4*)(Wr0 + off);
            sw1 = *(const float4*)(Wr1 + off);
        }

        #pragma unroll
        for (int k = 0; k < BKt; k++) {
            float a[8];
            *(float4*)&a[0] = *(const float4*)&As[k][ty * 8];
            *(float4*)&a[4] = *(const float4*)&As[k][ty * 8 + 4];
            const ull* wrow = (const ull*)&Ws[k][0];
            ull w0 = wrow[tx];
            ull w1 = wrow[tx + 16];
            ull w2 = wrow[tx + 32];
            ull w3 = wrow[tx + 48];
            #pragma unroll
            for (int i = 0; i < 8; i++) {
                ull ai = pack2(a[i], a[i]);
                ffma2(acc2[i][0], ai, w0);
                ffma2(acc2[i][1], ai, w1);
                ffma2(acc2[i][2], ai, w2);
                ffma2(acc2[i][3], ai, w3);
            }
        }
        __syncthreads();
    }

    int m0 = mBase + ty * 8;
    int nc = nBase + 2 * tx;
    float bsv[8];
    #pragma unroll
    for (int j = 0; j < 4; j++) {
        bsv[2 * j]     = bias[nc + 32 * j];
        bsv[2 * j + 1] = bias[nc + 32 * j + 1];
    }
    #pragma unroll
    for (int i = 0; i < 8; i++) {
        size_t rowOff = (size_t)(m0 + i) * N + nc;
        #pragma unroll
        for (int j = 0; j < 4; j++) {
            float lo, hi;
            unpack2(acc2[i][j], lo, hi);
            float2 st;
            st.x = act_elu(lo + bsv[2 * j], act);
            st.y = act_elu(hi + bsv[2 * j + 1], act);
            *(float2*)&C[rowOff + 32 * j] = st;
        }
    }
}

__device__ __forceinline__ void gemm_nn_core(const float* __restrict__ A,
                                             const float* __restrict__ Bm,
                                             const float* __restrict__ bias_m,
                                             float* __restrict__ C,
                                             int mBase, int nBase, int N, int K) {
    __shared__ float As[BKt][BM];
    __shared__ float Bs[BKt][BN];
    int tid = threadIdx.x;
    int tx = tid & 15, ty = tid >> 4;
    int lrow0 = tid >> 2, lc4 = (tid & 3) * 4;
    int bkr = tid >> 5, bc = (tid & 31) * 4;

    ull acc2[8][4];
    #pragma unroll
    for (int i = 0; i < 8; i++)
        #pragma unroll
        for (int j = 0; j < 4; j++) acc2[i][j] = 0ull;

    const float* Ar0 = A + (size_t)(mBase + lrow0) * K + lc4;
    const float* Ar1 = A + (size_t)(mBase + 64 + lrow0) * K + lc4;

    float4 sa0 = *(const float4*)Ar0;
    float4 sa1 = *(const float4*)Ar1;
    float4 sb0 = *(const float4*)&Bm[(size_t)(bkr) * N + nBase + bc];
    float4 sb1 = *(const float4*)&Bm[(size_t)(bkr + 8) * N + nBase + bc];

    for (int k0 = 0; k0 < K; k0 += BKt) {
        As[lc4 + 0][lrow0] = sa0.x; As[lc4 + 1][lrow0] = sa0.y; As[lc4 + 2][lrow0] = sa0.z; As[lc4 + 3][lrow0] = sa0.w;
        As[lc4 + 0][64 + lrow0] = sa1.x; As[lc4 + 1][64 + lrow0] = sa1.y; As[lc4 + 2][64 + lrow0] = sa1.z; As[lc4 + 3][64 + lrow0] = sa1.w;
        *(float4*)&Bs[bkr][bc] = sb0;
        *(float4*)&Bs[bkr + 8][bc] = sb1;
        __syncthreads();

        if (k0 + BKt < K) {
            int kn = k0 + BKt;
            sa0 = *(const float4*)(Ar0 + kn);
            sa1 = *(const float4*)(Ar1 + kn);
            sb0 = *(const float4*)&Bm[(size_t)(kn + bkr) * N + nBase + bc];
            sb1 = *(const float4*)&Bm[(size_t)(kn + bkr + 8) * N + nBase + bc];
        }

        #pragma unroll
        for (int k = 0; k < BKt; k++) {
            float a[8];
            *(float4*)&a[0] = *(const float4*)&As[k][ty * 8];
            *(float4*)&a[4] = *(const float4*)&As[k][ty * 8 + 4];
            const ull* wrow = (const ull*)&Bs[k][0];
            ull w0 = wrow[tx];
            ull w1 = wrow[tx + 16];
            ull w2 = wrow[tx + 32];
            ull w3 = wrow[tx + 48];
            #pragma unroll
            for (int i = 0; i < 8; i++) {
                ull ai = pack2(a[i], a[i]);
                ffma2(acc2[i][0], ai, w0);
                ffma2(acc2[i][1], ai, w1);
                ffma2(acc2[i][2], ai, w2);
                ffma2(acc2[i][3], ai, w3);
            }
        }
        __syncthreads();
    }

    int m0 = mBase + ty * 8;
    int nc = nBase + 2 * tx;
    #pragma unroll
    for (int i = 0; i < 8; i++) {
        float bm = bias_m[m0 + i];
        size_t rowOff = (size_t)(m0 + i) * N + nc;
        #pragma unroll
        for (int j = 0; j < 4; j++) {
            float lo, hi;
            unpack2(acc2[i][j], lo, hi);
            float2 st;
            st.x = act_elu(lo + bm, 1);
            st.y = act_elu(hi + bm, 1);
            *(float2*)&C[rowOff + 32 * j] = st;
        }
    }
}

// ---------------- mega-GEMM: lf + af2 + qkv + af3 in ONE launch (2048 blocks) ----
__global__ __launch_bounds__(256) void mega_gemm(const float* __restrict__ x1,
                                                 const float* __restrict__ x2,
                                                 const float* __restrict__ lf_w, const float* __restrict__ lf_b,
                                                 const float* __restrict__ af2_w, const float* __restrict__ af2_b,
                                                 const float* __restrict__ af3_w, const float* __restrict__ af3_b,
                                                 const float* __restrict__ attn_in_w, const float* __restrict__ attn_in_b,
                                                 float* __restrict__ p_lf, float* __restrict__ p_xout,
                                                 float* __restrict__ p_xout2, float* __restrict__ p_qkv) {
    int blk = blockIdx.x;
    int tid = threadIdx.x;
    int lrow0 = tid >> 2, lc4 = (tid & 3) * 4;

    if (blk < 1792) {
        const float* W; const float* bias; float* C;
        int nBase, mBase, N, act;
        bool catA;
        if (blk < 384) {
            nBase = (blk & 1) * BN; mBase = (blk >> 1) * BM;
            W = lf_w; bias = lf_b; C = p_lf; N = Dd; act = 1; catA = true;
        } else if (blk < 640) {
            int r = blk - 384;
            nBase = (r & 1) * BN; mBase = (r >> 1) * BM;
            W = af2_w; bias = af2_b; C = p_xout; N = Dd; act = 1; catA = false;
        } else {
            int r = blk - 640;
            nBase = (r % 6) * BN; mBase = (r / 6) * BM;
            W = attn_in_w; bias = attn_in_b; C = p_qkv; N = 3 * Dd; act = 0; catA = true;
        }
        const float* base;
        if (catA) {
            int b = mBase / Ss;
            int s0 = mBase - b * Ss;
            if (s0 < N1) base = x1 + ((size_t)b * N1 + s0) * Dd;
            else         base = x2 + ((size_t)b * N2 + (s0 - N1)) * Dd;
        } else {
            base = x1 + (size_t)mBase * Dd;
        }
        const float* Ar0 = base + (size_t)lrow0 * Dd + lc4;
        const float* Ar1 = base + (size_t)(64 + lrow0) * Dd + lc4;
        gemm_nt_core(Ar0, Ar1, W, bias, C, mBase, nBase, N, Dd, act);
    } else {
        int r = blk - 1792;
        int nBase = (r & 1) * BN;
        int m = r >> 1;
        int mBase = (m & 3) * BM;
        int bb = m >> 2;
        gemm_nn_core(af3_w, x2 + (size_t)bb * N2 * Dd, af3_b,
                     p_xout2 + (size_t)bb * N1 * Dd, mBase, nBase, Dd, N2);
    }
}

// ---------------- attn_out GEMM + fused router combine epilogue ----------------
__global__ __launch_bounds__(256) void gemm_out_combine(const float* __restrict__ A,
                                                        const float* __restrict__ W,
                                                        const float* __restrict__ bias,
                                                        const float* __restrict__ x1,
                                                        const float* __restrict__ x2,
                                                        float* __restrict__ out) {
    __shared__ float As[BKt][BM];
    __shared__ float Ws[BKt][BN];
    int tid = threadIdx.x;
    int nBase = blockIdx.x * BN;
    int mBase = blockIdx.y * BM;
    int tx = tid & 15, ty = tid >> 4;
    int lrow0 = tid >> 2, lc4 = (tid & 3) * 4;
    const int N = Dd, K = Dd;

    ull acc2[8][4];
    #pragma unroll
    for (int i = 0; i < 8; i++)
        #pragma unroll
        for (int j = 0; j < 4; j++) acc2[i][j] = 0ull;

    const float* Ar0 = A + (size_t)(mBase + lrow0) * K + lc4;
    const float* Ar1 = A + (size_t)(mBase + 64 + lrow0) * K + lc4;
    const float* Wr0 = W + (size_t)(nBase + lrow0) * K + lc4;
    const float* Wr1 = W + (size_t)(nBase + 64 + lrow0) * K + lc4;

    float4 sa0 = *(const float4*)Ar0;
    float4 sa1 = *(const float4*)Ar1;
    float4 sw0 = *(const float4*)Wr0;
    float4 sw1 = *(const float4*)Wr1;

    for (int k0 = 0; k0 < K; k0 += BKt) {
        As[lc4 + 0][lrow0] = sa0.x; As[lc4 + 1][lrow0] = sa0.y; As[lc4 + 2][lrow0] = sa0.z; As[lc4 + 3][lrow0] = sa0.w;
        As[lc4 + 0][64 + lrow0] = sa1.x; As[lc4 + 1][64 + lrow0] = sa1.y; As[lc4 + 2][64 + lrow0] = sa1.z; As[lc4 + 3][64 + lrow0] = sa1.w;
        Ws[lc4 + 0][lrow0] = sw0.x; Ws[lc4 + 1][lrow0] = sw0.y; Ws[lc4 + 2][lrow0] = sw0.z; Ws[lc4 + 3][lrow0] = sw0.w;
        Ws[lc4 + 0][64 + lrow0] = sw1.x; Ws[lc4 + 1][64 + lrow0] = sw1.y; Ws[lc4 + 2][64 + lrow0] = sw1.z; Ws[lc4 + 3][64 + lrow0] = sw1.w;
        __syncthreads();

        if (k0 + BKt < K) {
            int off = k0 + BKt;
            sa0 = *(const float4*)(Ar0 + off);
            sa1 = *(const float4*)(Ar1 + off);
            sw0 = *(const float4*)(Wr0 + off);
            sw1 = *(const float4*)(Wr1 + off);
        }

        #pragma unroll
        for (int k = 0; k < BKt; k++) {
            float a[8];
            *(float4*)&a[0] = *(const float4*)&As[k][ty * 8];
            *(float4*)&a[4] = *(const float4*)&As[k][ty * 8 + 4];
            const ull* wrow = (const ull*)&Ws[k][0];
            ull w0 = wrow[tx];
            ull w1 = wrow[tx + 16];
            ull w2 = wrow[tx + 32];
            ull w3 = wrow[tx + 48];
            #pragma unroll
            for (int i = 0; i < 8; i++) {
                ull ai = pack2(a[i], a[i]);
                ffma2(acc2[i][0], ai, w0);
                ffma2(acc2[i][1], ai, w1);
                ffma2(acc2[i][2], ai, w2);
                ffma2(acc2[i][3], ai, w3);
            }
        }
        __syncthreads();
    }

    int m0 = mBase + ty * 8;
    int nc = nBase + 2 * tx;
    float bsv[8];
    #pragma unroll
    for (int j = 0; j < 4; j++) {
        bsv[2 * j]     = bias[nc + 32 * j];
        bsv[2 * j + 1] = bias[nc + 32 * j + 1];
    }
    const size_t GENE = (size_t)Bsz * N1 * Dd;
    #pragma unroll
    for (int i = 0; i < 8; i++) {
        int row = m0 + i;
        int b = row / Ss;
        int s = row - b * Ss;
        const float* wp = g_w + b * 4;
        float rw0 = wp[0], rw1 = wp[1], rw2 = wp[2], rw3 = wp[3];
        const float* lfp = g_lf + (size_t)row * Dd;
        const float* xp; const float* xop; const float* xo2p; float* outp;
        if (s < N1) {
            size_t off = ((size_t)b * N1 + s) * Dd;
            xp = x1 + off; xop = g_xout + off; xo2p = g_xout2 + off; outp = out + off;
        } else {
            int n = s - N1;
            size_t xoff = ((size_t)b * N1 + n) * Dd;
            size_t ioff = ((size_t)b * N2 + n) * Dd;
            xp = x2 + ioff; xop = g_xout + xoff; xo2p = g_xout2 + xoff; outp = out + GENE + ioff;
        }
        #pragma unroll
        for (int j = 0; j < 4; j++) {
            float lo, hi;
            unpack2(acc2[i][j], lo, hi);
            int c0 = nc + 32 * j;
            float o0 = lo + bsv[2 * j];
            float o1 = hi + bsv[2 * j + 1];
            float2 st;
            st.x = rw0 * lfp[c0]     + rw1 * (xop[c0]     + xo2p[c0])     + rw2 * o0 + rw3 * xp[c0];
            st.y = rw0 * lfp[c0 + 1] + rw1 * (xop[c0 + 1] + xo2p[c0 + 1]) + rw2 * o1 + rw3 * xp[c0 + 1];
            *(float2*)&outp[c0] = st;
        }
    }
}

// ---------------- attention v7: 8 queries/warp with key-range split ----------------
// Warp pair (2p, 2p+1) shares queries qbase=qc*32+p*8; warp half=w&1 handles keys
// [half*384, half*384+384). Scores s2[8][6] (96 regs). Max-free softmax: partial
// exp-sums just add across halves. PV partials pair-added via smem (reusing Qd).
#define KTP 770

__global__ __launch_bounds__(256, 2) void attn_kernel(const float* __restrict__ qkv,
                                                      float* __restrict__ oattn) {
    extern __shared__ float smem[];
    float* KV = smem;                     // 32 * 770 floats, K then V
    ull* Qd = (ull*)(KV + 32 * KTP);      // 4 pairs * 256 ull  (8KB); reused for PV partials
    float* Sb = (float*)(Qd + 1024);      // 8 warps * 8 floats (partial exp-sums)
    int blk = blockIdx.x;
    int b = blk >> 3, h = blk & 7;
    int qc = blockIdx.y;                  // 0..23
    int tid = threadIdx.x, lane = tid & 31, w = tid >> 5;
    int p = w >> 1, half = w & 1;
    const float* base = qkv + (size_t)b * Ss * (3 * Dd);

    // ---- load K transposed via float4 ----
    for (int it = tid; it < Ss * 8; it += 256) {
        int j = it >> 3, c = it & 7;
        float4 v = *(const float4*)&base[(size_t)j * (3 * Dd) + Dd + h * HD + 4 * c];
        KV[(4 * c + 0) * KTP + j] = v.x;
        KV[(4 * c + 1) * KTP + j] = v.y;
        KV[(4 * c + 2) * KTP + j] = v.z;
        KV[(4 * c + 3) * KTP + j] = v.w;
    }

    // ---- stage 8 scaled queries per pair, [d][i]-major packed (half==0 writes) ----
    const float scale = 0.17677669529663687f; // 1/sqrt(32)
    int qbase = qc * 32 + p * 8;
    ull* Qp = Qd + p * 256;
    if (half == 0) {
        #pragma unroll
        for (int i = 0; i < 8; i++) {
            float qv = base[(size_t)(qbase + i) * (3 * Dd) + h * HD + lane] * scale;
            Qp[lane * 8 + i] = pack2(qv, qv);
        }
    }
    __syncthreads();

    // ---- QK^T over this warp's half of the keys ----
    // key pair for (t, lane): j = half*384 + 64t + 2lane  -> ull index half*192 + 32t + lane
    ull s2[8][6];
    #pragma unroll
    for (int i = 0; i < 8; i++)
        #pragma unroll
        for (int t = 0; t < 6; t++) s2[i][t] = 0ull;

    #pragma unroll 2
    for (int d = 0; d < 32; d++) {
        ulonglong2 qa = *(const ulonglong2*)(Qp + d * 8);      // q0,q1
        ulonglong2 qb = *(const ulonglong2*)(Qp + d * 8 + 2);  // q2,q3
        ulonglong2 qc2 = *(const ulonglong2*)(Qp + d * 8 + 4); // q4,q5
        ulonglong2 qd2 = *(const ulonglong2*)(Qp + d * 8 + 6); // q6,q7
        const ull* kr = (const ull*)(KV + d * KTP) + half * 192 + lane;
        #pragma unroll
        for (int t = 0; t < 6; t++) {
            ull k2 = kr[32 * t];
            ffma2(s2[0][t], qa.x, k2);
            ffma2(s2[1][t], qa.y, k2);
            ffma2(s2[2][t], qb.x, k2);
            ffma2(s2[3][t], qb.y, k2);
            ffma2(s2[4][t], qc2.x, k2);
            ffma2(s2[5][t], qc2.y, k2);
            ffma2(s2[6][t], qd2.x, k2);
            ffma2(s2[7][t], qd2.y, k2);
        }
    }

    // ---- exp + partial sums (max-free) ----
    float psum[8];
    #pragma unroll
    for (int i = 0; i < 8; i++) {
        float lo, hi;
        float sum = 0.f;
        #pragma unroll
        for (int t = 0; t < 6; t++) {
            unpack2(s2[i][t], lo, hi);
            lo = __expf(lo); hi = __expf(hi);
            sum += lo + hi;
            s2[i][t] = pack2(lo, hi);
        }
        #pragma unroll
        for (int o = 16; o; o >>= 1) sum += __shfl_xor_sync(0xffffffffu, sum, o);
        psum[i] = sum;
    }
    if (lane < 8) Sb[w * 8 + lane] = psum[lane];

    // ---- barrier: QK reads done + partial sums visible; then fill V + normalize ----
    __syncthreads();
    #pragma unroll
    for (int i = 0; i < 8; i++) {
        float tot = psum[i] + Sb[(w ^ 1) * 8 + i];
        float iv = 1.f / tot;
        ull iv2 = pack2(iv, iv);
        #pragma unroll
        for (int t = 0; t < 6; t++) s2[i][t] = mul2(s2[i][t], iv2);
    }
    for (int it = tid; it < Ss * 8; it += 256) {
        int j = it >> 3, c = it & 7;
        float4 v = *(const float4*)&base[(size_t)j * (3 * Dd) + 2 * Dd + h * HD + 4 * c];
        KV[(4 * c + 0) * KTP + j] = v.x;
        KV[(4 * c + 1) * KTP + j] = v.y;
        KV[(4 * c + 2) * KTP + j] = v.z;
        KV[(4 * c + 3) * KTP + j] = v.w;
    }
    __syncthreads();

    // ---- PV over this warp's half; packed butterfly; lane==d keeps 8 partials ----
    float o[8];
    #pragma unroll
    for (int i = 0; i < 8; i++) o[i] = 0.f;
    for (int d = 0; d < 32; d++) {
        const ull* vr = (const ull*)(KV + d * KTP) + half * 192 + lane;
        ull a0 = 0ull, a1 = 0ull, a2 = 0ull, a3 = 0ull, a4 = 0ull, a5 = 0ull, a6 = 0ull, a7 = 0ull;
        #pragma unroll
        for (int t = 0; t < 6; t++) {
            ull v2 = vr[32 * t];
            ffma2(a0, s2[0][t], v2);
            ffma2(a1, s2[1][t], v2);
            ffma2(a2, s2[2][t], v2);
            ffma2(a3, s2[3][t], v2);
            ffma2(a4, s2[4][t], v2);
            ffma2(a5, s2[5][t], v2);
            ffma2(a6, s2[6][t], v2);
            ffma2(a7, s2[7][t], v2);
        }
        float lo, hi, r0, r1, r2, r3, r4, r5, r6, r7;
        unpack2(a0, lo, hi); r0 = lo + hi;
        unpack2(a1, lo, hi); r1 = lo + hi;
        unpack2(a2, lo, hi); r2 = lo + hi;
        unpack2(a3, lo, hi); r3 = lo + hi;
        unpack2(a4, lo, hi); r4 = lo + hi;
        unpack2(a5, lo, hi); r5 = lo + hi;
        unpack2(a6, lo, hi); r6 = lo + hi;
        unpack2(a7, lo, hi); r7 = lo + hi;
        ull p01 = pack2(r0, r1), p23 = pack2(r2, r3), p45 = pack2(r4, r5), p67 = pack2(r6, r7);
        #pragma unroll
        for (int os = 16; os; os >>= 1) {
            p01 = add2(p01, __shfl_xor_sync(0xffffffffu, p01, os));
            p23 = add2(p23, __shfl_xor_sync(0xffffffffu, p23, os));
            p45 = add2(p45, __shfl_xor_sync(0xffffffffu, p45, os));
            p67 = add2(p67, __shfl_xor_sync(0xffffffffu, p67, os));
        }
        if (lane == d) {
            unpack2(p01, o[0], o[1]);
            unpack2(p23, o[2], o[3]);
            unpack2(p45, o[4], o[5]);
            unpack2(p67, o[6], o[7]);
        }
    }

    // ---- pair-reduce partials via smem (reuse Qd region) ----
    float* Pb = (float*)Qd;               // 8 warps * 256 floats
    #pragma unroll
    for (int i = 0; i < 8; i++) Pb[w * 256 + i * 32 + lane] = o[i];
    __syncthreads();
    // warp w stores queries [half*4, half*4+4) of its pair
    #pragma unroll
    for (int i = 0; i < 4; i++) {
        int q = half * 4 + i;
        float v = Pb[(2 * p) * 256 + q * 32 + lane] + Pb[(2 * p + 1) * 256 + q * 32 + lane];
        oattn[((size_t)b * Ss + qbase + q) * Dd + h * HD + lane] = v;
    }
}

// ---------------- launch ----------------
extern "C" void kernel_launch(void* const* d_in, const int* in_sizes, int n_in,
                              void* d_out, int out_size) {
    const float* x1        = (const float*)d_in[0];
    const float* x2        = (const float*)d_in[1];
    const float* r_w1      = (const float*)d_in[2];
    const float* r_b1      = (const float*)d_in[3];
    const float* ln_g      = (const float*)d_in[4];
    const float* ln_b      = (const float*)d_in[5];
    const float* r_w2      = (const float*)d_in[6];
    const float* r_b2      = (const float*)d_in[7];
    const float* lf_w      = (const float*)d_in[8];
    const float* lf_b      = (const float*)d_in[9];
    const float* af2_w     = (const float*)d_in[10];
    const float* af2_b     = (const float*)d_in[11];
    const float* af3_w     = (const float*)d_in[12];
    const float* af3_b     = (const float*)d_in[13];
    const float* attn_in_w = (const float*)d_in[14];
    const float* attn_in_b = (const float*)d_in[15];
    const float* attn_out_w= (const float*)d_in[16];
    const float* attn_out_b= (const float*)d_in[17];
    float* out = (float*)d_out;

    float *p_lf, *p_xout, *p_xout2, *p_qkv, *p_oattn;
    cudaGetSymbolAddress((void**)&p_lf, g_lf);
    cudaGetSymbolAddress((void**)&p_xout, g_xout);
    cudaGetSymbolAddress((void**)&p_xout2, g_xout2);
    cudaGetSymbolAddress((void**)&p_qkv, g_qkv);
    cudaGetSymbolAddress((void**)&p_oattn, g_oattn);

    const int ATTN_SMEM = (32 * KTP) * 4 + 1024 * 8 + 64 * 4; // 98560+8192+256 = 107008 B
    cudaFuncSetAttribute(attn_kernel, cudaFuncAttributeMaxDynamicSharedMemorySize, ATTN_SMEM);

    // means + router
    mean_kernel<<<dim3(Bsz, 2), 256>>>(x1, x2);
    router_kernel<<<Bsz, 256>>>(r_w1, r_b1, ln_g, ln_b, r_w2, r_b2);
    // fused: lf, af2, qkv, af3 (2048 blocks, one tail)
    mega_gemm<<<2048, 256>>>(x1, x2, lf_w, lf_b, af2_w, af2_b, af3_w, af3_b,
                             attn_in_w, attn_in_b, p_lf, p_xout, p_xout2, p_qkv);
    // attention (8 q/warp, key-split pairs)
    attn_kernel<<<dim3(Bsz * Hh, 24), 256, ATTN_SMEM>>>(p_qkv, p_oattn);
    // attn_out projection with fused router combine -> writes final output
    gemm_out_combine<<<dim3(Dd / BN, (Bsz * Ss) / BM), 256>>>(p_oattn, attn_out_w, attn_out_b,
                                                              x1, x2, out);
}

// round 14
// speedup vs baseline: 1.0349x; 1.0349x over previous
#include <cuda_runtime.h>
#include <math.h>
#include <stdint.h>

#define Bsz 32
#define N1 512
#define N2 256
#define Dd 256
#define Hh 8
#define HD 32
#define Ss 768
#define TWOD 512

typedef unsigned long long ull;

// ---------------- f32x2 packed-FMA helpers (sm_103a) ----------------
__device__ __forceinline__ ull pack2(float lo, float hi) {
    ull r; asm("mov.b64 %0, {%1, %2};" : "=l"(r) : "f"(lo), "f"(hi)); return r;
}
__device__ __forceinline__ void unpack2(ull v, float& lo, float& hi) {
    asm("mov.b64 {%0, %1}, %2;" : "=f"(lo), "=f"(hi) : "l"(v));
}
__device__ __forceinline__ void ffma2(ull& d, ull a, ull b) {
    asm("fma.rn.f32x2 %0, %1, %2, %0;" : "+l"(d) : "l"(a), "l"(b));
}
__device__ __forceinline__ ull mul2(ull a, ull b) {
    ull r; asm("mul.rn.f32x2 %0, %1, %2;" : "=l"(r) : "l"(a), "l"(b)); return r;
}
__device__ __forceinline__ ull add2(ull a, ull b) {
    ull r; asm("add.rn.f32x2 %0, %1, %2;" : "=l"(r) : "l"(a), "l"(b)); return r;
}

// ---------------- static scratch (no allocations allowed) ----------------
__device__ float g_m[Bsz * TWOD];
__device__ float g_w[Bsz * 4];
__device__ float g_lf[(size_t)Bsz * Ss * Dd];
__device__ float g_xout[(size_t)Bsz * N1 * Dd];
__device__ float g_xout2[(size_t)Bsz * N1 * Dd];
__device__ float g_qkv[(size_t)Bsz * Ss * 3 * Dd];
__device__ float g_oattn[(size_t)Bsz * Ss * Dd];

// ---------------- small kernels ----------------
__global__ void mean_kernel(const float* __restrict__ x1, const float* __restrict__ x2) {
    int b = blockIdx.x;
    int part = blockIdx.y;
    int d = threadIdx.x;
    if (part == 0) {
        const float* p = x1 + (size_t)b * N1 * Dd + d;
        float s = 0.f;
        for (int n = 0; n < N1; n++) s += p[(size_t)n * Dd];
        g_m[b * TWOD + d] = s * (1.0f / N1);
    } else {
        const float* p = x2 + (size_t)b * N2 * Dd + d;
        float s = 0.f;
        for (int n = 0; n < N2; n++) s += p[(size_t)n * Dd];
        g_m[b * TWOD + 256 + d] = s * (1.0f / N2);
    }
}

__global__ void router_kernel(const float* __restrict__ r_w1, const float* __restrict__ r_b1,
                              const float* __restrict__ ln_g, const float* __restrict__ ln_b,
                              const float* __restrict__ r_w2, const float* __restrict__ r_b2) {
    int b = blockIdx.x;
    int tid = threadIdx.x;
    __shared__ float ms[TWOD];
    __shared__ float red[256];
    __shared__ float hb[256];
    __shared__ float logits[4];
    ms[tid] = g_m[b * TWOD + tid];
    ms[tid + 256] = g_m[b * TWOD + 256 + tid];
    __syncthreads();
    float acc = r_b1[tid];
    const float* wr = r_w1 + (size_t)tid * TWOD;
    #pragma unroll 8
    for (int k = 0; k < TWOD; k++) acc = fmaf(ms[k], wr[k], acc);
    red[tid] = acc; __syncthreads();
    for (int s = 128; s > 0; s >>= 1) { if (tid < s) red[tid] += red[tid + s]; __syncthreads(); }
    float mu = red[0] * (1.0f / 256.0f); __syncthreads();
    float dv = acc - mu;
    red[tid] = dv * dv; __syncthreads();
    for (int s = 128; s > 0; s >>= 1) { if (tid < s) red[tid] += red[tid + s]; __syncthreads(); }
    float var = red[0] * (1.0f / 256.0f); __syncthreads();
    float xn = dv * rsqrtf(var + 1e-5f) * ln_g[tid] + ln_b[tid];
    float hv = 0.5f * xn * (1.0f + erff(xn * 0.70710678118654752f));
    hb[tid] = hv; __syncthreads();
    for (int e = 0; e < 4; e++) {
        red[tid] = hb[tid] * r_w2[e * 256 + tid]; __syncthreads();
        for (int s = 128; s > 0; s >>= 1) { if (tid < s) red[tid] += red[tid + s]; __syncthreads(); }
        if (tid == 0) logits[e] = red[0] + r_b2[e];
        __syncthreads();
    }
    if (tid == 0) {
        float mx = fmaxf(fmaxf(logits[0], logits[1]), fmaxf(logits[2], logits[3]));
        float e0 = expf(logits[0] - mx), e1 = expf(logits[1] - mx);
        float e2 = expf(logits[2] - mx), e3 = expf(logits[3] - mx);
        float inv = 1.0f / (e0 + e1 + e2 + e3);
        g_w[b * 4 + 0] = e0 * inv; g_w[b * 4 + 1] = e1 * inv;
        g_w[b * 4 + 2] = e2 * inv; g_w[b * 4 + 3] = e3 * inv;
    }
}

// ---------------- GEMM cores (R8-proven inner loop, runtime act) ----------------
#define BM 128
#define BN 128
#define BKt 16

__device__ __forceinline__ float act_elu(float v, int act) {
    return (act && v <= 0.f) ? expm1f(v) : v;
}

__device__ __forceinline__ void gemm_nt_core(const float* Ar0, const float* Ar1,
                                             const float* __restrict__ W,
                                             const float* __restrict__ bias,
                                             float* __restrict__ C,
                                             int mBase, int nBase, int N, int K, int act) {
    __shared__ float As[BKt][BM];
    __shared__ float Ws[BKt][BN];
    int tid = threadIdx.x;
    int tx = tid & 15, ty = tid >> 4;
    int lrow0 = tid >> 2, lc4 = (tid & 3) * 4;

    ull acc2[8][4];
    #pragma unroll
    for (int i = 0; i < 8; i++)
        #pragma unroll
        for (int j = 0; j < 4; j++) acc2[i][j] = 0ull;

    const float* Wr0 = W + (size_t)(nBase + lrow0) * K + lc4;
    const float* Wr1 = W + (size_t)(nBase + 64 + lrow0) * K + lc4;

    float4 sa0 = *(const float4*)Ar0;
    float4 sa1 = *(const float4*)Ar1;
    float4 sw0 = *(const float4*)Wr0;
    float4 sw1 = *(const float4*)Wr1;

    for (int k0 = 0; k0 < K; k0 += BKt) {
        As[lc4 + 0][lrow0] = sa0.x; As[lc4 + 1][lrow0] = sa0.y; As[lc4 + 2][lrow0] = sa0.z; As[lc4 + 3][lrow0] = sa0.w;
        As[lc4 + 0][64 + lrow0] = sa1.x; As[lc4 + 1][64 + lrow0] = sa1.y; As[lc4 + 2][64 + lrow0] = sa1.z; As[lc4 + 3][64 + lrow0] = sa1.w;
        Ws[lc4 + 0][lrow0] = sw0.x; Ws[lc4 + 1][lrow0] = sw0.y; Ws[lc4 + 2][lrow0] = sw0.z; Ws[lc4 + 3][lrow0] = sw0.w;
        Ws[lc4 + 0][64 + lrow0] = sw1.x; Ws[lc4 + 1][64 + lrow0] = sw1.y; Ws[lc4 + 2][64 + lrow0] = sw1.z; Ws[lc4 + 3][64 + lrow0] = sw1.w;
        __syncthreads();

        if (k0 + BKt < K) {
            int off = k0 + BKt;
            sa0 = *(const float4*)(Ar0 + off);
            sa1 = *(const float4*)(Ar1 + off);
            sw0 = *(const float4*)(Wr0 + off);
            sw1 = *(const float4*)(Wr1 + off);
        }

        #pragma unroll
        for (int k = 0; k < BKt; k++) {
            float a[8];
            *(float4*)&a[0] = *(const float4*)&As[k][ty * 8];
            *(float4*)&a[4] = *(const float4*)&As[k][ty * 8 + 4];
            const ull* wrow = (const ull*)&Ws[k][0];
            ull w0 = wrow[tx];
            ull w1 = wrow[tx + 16];
            ull w2 = wrow[tx + 32];
            ull w3 = wrow[tx + 48];
            #pragma unroll
            for (int i = 0; i < 8; i++) {
                ull ai = pack2(a[i], a[i]);
                ffma2(acc2[i][0], ai, w0);
                ffma2(acc2[i][1], ai, w1);
                ffma2(acc2[i][2], ai, w2);
                ffma2(acc2[i][3], ai, w3);
            }
        }
        __syncthreads();
    }

    int m0 = mBase + ty * 8;
    int nc = nBase + 2 * tx;
    float bsv[8];
    #pragma unroll
    for (int j = 0; j < 4; j++) {
        bsv[2 * j]     = bias[nc + 32 * j];
        bsv[2 * j + 1] = bias[nc + 32 * j + 1];
    }
    #pragma unroll
    for (int i = 0; i < 8; i++) {
        size_t rowOff = (size_t)(m0 + i) * N + nc;
        #pragma unroll
        for (int j = 0; j < 4; j++) {
            float lo, hi;
            unpack2(acc2[i][j], lo, hi);
            float2 st;
            st.x = act_elu(lo + bsv[2 * j], act);
            st.y = act_elu(hi + bsv[2 * j + 1], act);
            *(float2*)&C[rowOff + 32 * j] = st;
        }
    }
}

__device__ __forceinline__ void gemm_nn_core(const float* __restrict__ A,
                                             const float* __restrict__ Bm,
                                             const float* __restrict__ bias_m,
                                             float* __restrict__ C,
                                             int mBase, int nBase, int N, int K) {
    __shared__ float As[BKt][BM];
    __shared__ float Bs[BKt][BN];
    int tid = threadIdx.x;
    int tx = tid & 15, ty = tid >> 4;
    int lrow0 = tid >> 2, lc4 = (tid & 3) * 4;
    int bkr = tid >> 5, bc = (tid & 31) * 4;

    ull acc2[8][4];
    #pragma unroll
    for (int i = 0; i < 8; i++)
        #pragma unroll
        for (int j = 0; j < 4; j++) acc2[i][j] = 0ull;

    const float* Ar0 = A + (size_t)(mBase + lrow0) * K + lc4;
    const float* Ar1 = A + (size_t)(mBase + 64 + lrow0) * K + lc4;

    float4 sa0 = *(const float4*)Ar0;
    float4 sa1 = *(const float4*)Ar1;
    float4 sb0 = *(const float4*)&Bm[(size_t)(bkr) * N + nBase + bc];
    float4 sb1 = *(const float4*)&Bm[(size_t)(bkr + 8) * N + nBase + bc];

    for (int k0 = 0; k0 < K; k0 += BKt) {
        As[lc4 + 0][lrow0] = sa0.x; As[lc4 + 1][lrow0] = sa0.y; As[lc4 + 2][lrow0] = sa0.z; As[lc4 + 3][lrow0] = sa0.w;
        As[lc4 + 0][64 + lrow0] = sa1.x; As[lc4 + 1][64 + lrow0] = sa1.y; As[lc4 + 2][64 + lrow0] = sa1.z; As[lc4 + 3][64 + lrow0] = sa1.w;
        *(float4*)&Bs[bkr][bc] = sb0;
        *(float4*)&Bs[bkr + 8][bc] = sb1;
        __syncthreads();

        if (k0 + BKt < K) {
            int kn = k0 + BKt;
            sa0 = *(const float4*)(Ar0 + kn);
            sa1 = *(const float4*)(Ar1 + kn);
            sb0 = *(const float4*)&Bm[(size_t)(kn + bkr) * N + nBase + bc];
            sb1 = *(const float4*)&Bm[(size_t)(kn + bkr + 8) * N + nBase + bc];
        }

        #pragma unroll
        for (int k = 0; k < BKt; k++) {
            float a[8];
            *(float4*)&a[0] = *(const float4*)&As[k][ty * 8];
            *(float4*)&a[4] = *(const float4*)&As[k][ty * 8 + 4];
            const ull* wrow = (const ull*)&Bs[k][0];
            ull w0 = wrow[tx];
            ull w1 = wrow[tx + 16];
            ull w2 = wrow[tx + 32];
            ull w3 = wrow[tx + 48];
            #pragma unroll
            for (int i = 0; i < 8; i++) {
                ull ai = pack2(a[i], a[i]);
                ffma2(acc2[i][0], ai, w0);
                ffma2(acc2[i][1], ai, w1);
                ffma2(acc2[i][2], ai, w2);
                ffma2(acc2[i][3], ai, w3);
            }
        }
        __syncthreads();
    }

    int m0 = mBase + ty * 8;
    int nc = nBase + 2 * tx;
    #pragma unroll
    for (int i = 0; i < 8; i++) {
        float bm = bias_m[m0 + i];
        size_t rowOff = (size_t)(m0 + i) * N + nc;
        #pragma unroll
        for (int j = 0; j < 4; j++) {
            float lo, hi;
            unpack2(acc2[i][j], lo, hi);
            float2 st;
            st.x = act_elu(lo + bm, 1);
            st.y = act_elu(hi + bm, 1);
            *(float2*)&C[rowOff + 32 * j] = st;
        }
    }
}

// ---------------- mega-GEMM: lf + af2 + qkv + af3 in ONE launch (2048 blocks) ----
__global__ __launch_bounds__(256) void mega_gemm(const float* __restrict__ x1,
                                                 const float* __restrict__ x2,
                                                 const float* __restrict__ lf_w, const float* __restrict__ lf_b,
                                                 const float* __restrict__ af2_w, const float* __restrict__ af2_b,
                                                 const float* __restrict__ af3_w, const float* __restrict__ af3_b,
                                                 const float* __restrict__ attn_in_w, const float* __restrict__ attn_in_b,
                                                 float* __restrict__ p_lf, float* __restrict__ p_xout,
                                                 float* __restrict__ p_xout2, float* __restrict__ p_qkv) {
    int blk = blockIdx.x;
    int tid = threadIdx.x;
    int lrow0 = tid >> 2, lc4 = (tid & 3) * 4;

    if (blk < 1792) {
        const float* W; const float* bias; float* C;
        int nBase, mBase, N, act;
        bool catA;
        if (blk < 384) {
            nBase = (blk & 1) * BN; mBase = (blk >> 1) * BM;
            W = lf_w; bias = lf_b; C = p_lf; N = Dd; act = 1; catA = true;
        } else if (blk < 640) {
            int r = blk - 384;
            nBase = (r & 1) * BN; mBase = (r >> 1) * BM;
            W = af2_w; bias = af2_b; C = p_xout; N = Dd; act = 1; catA = false;
        } else {
            int r = blk - 640;
            nBase = (r % 6) * BN; mBase = (r / 6) * BM;
            W = attn_in_w; bias = attn_in_b; C = p_qkv; N = 3 * Dd; act = 0; catA = true;
        }
        const float* base;
        if (catA) {
            int b = mBase / Ss;
            int s0 = mBase - b * Ss;
            if (s0 < N1) base = x1 + ((size_t)b * N1 + s0) * Dd;
            else         base = x2 + ((size_t)b * N2 + (s0 - N1)) * Dd;
        } else {
            base = x1 + (size_t)mBase * Dd;
        }
        const float* Ar0 = base + (size_t)lrow0 * Dd + lc4;
        const float* Ar1 = base + (size_t)(64 + lrow0) * Dd + lc4;
        gemm_nt_core(Ar0, Ar1, W, bias, C, mBase, nBase, N, Dd, act);
    } else {
        int r = blk - 1792;
        int nBase = (r & 1) * BN;
        int m = r >> 1;
        int mBase = (m & 3) * BM;
        int bb = m >> 2;
        gemm_nn_core(af3_w, x2 + (size_t)bb * N2 * Dd, af3_b,
                     p_xout2 + (size_t)bb * N1 * Dd, mBase, nBase, Dd, N2);
    }
}

// ---------------- attn_out GEMM + fused router combine epilogue ----------------
__global__ __launch_bounds__(256) void gemm_out_combine(const float* __restrict__ A,
                                                        const float* __restrict__ W,
                                                        const float* __restrict__ bias,
                                                        const float* __restrict__ x1,
                                                        const float* __restrict__ x2,
                                                        float* __restrict__ out) {
    __shared__ float As[BKt][BM];
    __shared__ float Ws[BKt][BN];
    int tid = threadIdx.x;
    int nBase = blockIdx.x * BN;
    int mBase = blockIdx.y * BM;
    int tx = tid & 15, ty = tid >> 4;
    int lrow0 = tid >> 2, lc4 = (tid & 3) * 4;
    const int N = Dd, K = Dd;

    ull acc2[8][4];
    #pragma unroll
    for (int i = 0; i < 8; i++)
        #pragma unroll
        for (int j = 0; j < 4; j++) acc2[i][j] = 0ull;

    const float* Ar0 = A + (size_t)(mBase + lrow0) * K + lc4;
    const float* Ar1 = A + (size_t)(mBase + 64 + lrow0) * K + lc4;
    const float* Wr0 = W + (size_t)(nBase + lrow0) * K + lc4;
    const float* Wr1 = W + (size_t)(nBase + 64 + lrow0) * K + lc4;

    float4 sa0 = *(const float4*)Ar0;
    float4 sa1 = *(const float4*)Ar1;
    float4 sw0 = *(const float4*)Wr0;
    float4 sw1 = *(const float4*)Wr1;

    for (int k0 = 0; k0 < K; k0 += BKt) {
        As[lc4 + 0][lrow0] = sa0.x; As[lc4 + 1][lrow0] = sa0.y; As[lc4 + 2][lrow0] = sa0.z; As[lc4 + 3][lrow0] = sa0.w;
        As[lc4 + 0][64 + lrow0] = sa1.x; As[lc4 + 1][64 + lrow0] = sa1.y; As[lc4 + 2][64 + lrow0] = sa1.z; As[lc4 + 3][64 + lrow0] = sa1.w;
        Ws[lc4 + 0][lrow0] = sw0.x; Ws[lc4 + 1][lrow0] = sw0.y; Ws[lc4 + 2][lrow0] = sw0.z; Ws[lc4 + 3][lrow0] = sw0.w;
        Ws[lc4 + 0][64 + lrow0] = sw1.x; Ws[lc4 + 1][64 + lrow0] = sw1.y; Ws[lc4 + 2][64 + lrow0] = sw1.z; Ws[lc4 + 3][64 + lrow0] = sw1.w;
        __syncthreads();

        if (k0 + BKt < K) {
            int off = k0 + BKt;
            sa0 = *(const float4*)(Ar0 + off);
            sa1 = *(const float4*)(Ar1 + off);
            sw0 = *(const float4*)(Wr0 + off);
            sw1 = *(const float4*)(Wr1 + off);
        }

        #pragma unroll
        for (int k = 0; k < BKt; k++) {
            float a[8];
            *(float4*)&a[0] = *(const float4*)&As[k][ty * 8];
            *(float4*)&a[4] = *(const float4*)&As[k][ty * 8 + 4];
            const ull* wrow = (const ull*)&Ws[k][0];
            ull w0 = wrow[tx];
            ull w1 = wrow[tx + 16];
            ull w2 = wrow[tx + 32];
            ull w3 = wrow[tx + 48];
            #pragma unroll
            for (int i = 0; i < 8; i++) {
                ull ai = pack2(a[i], a[i]);
                ffma2(acc2[i][0], ai, w0);
                ffma2(acc2[i][1], ai, w1);
                ffma2(acc2[i][2], ai, w2);
                ffma2(acc2[i][3], ai, w3);
            }
        }
        __syncthreads();
    }

    int m0 = mBase + ty * 8;
    int nc = nBase + 2 * tx;
    float bsv[8];
    #pragma unroll
    for (int j = 0; j < 4; j++) {
        bsv[2 * j]     = bias[nc + 32 * j];
        bsv[2 * j + 1] = bias[nc + 32 * j + 1];
    }
    const size_t GENE = (size_t)Bsz * N1 * Dd;
    #pragma unroll
    for (int i = 0; i < 8; i++) {
        int row = m0 + i;
        int b = row / Ss;
        int s = row - b * Ss;
        const float* wp = g_w + b * 4;
        float rw0 = wp[0], rw1 = wp[1], rw2 = wp[2], rw3 = wp[3];
        const float* lfp = g_lf + (size_t)row * Dd;
        const float* xp; const float* xop; const float* xo2p; float* outp;
        if (s < N1) {
            size_t off = ((size_t)b * N1 + s) * Dd;
            xp = x1 + off; xop = g_xout + off; xo2p = g_xout2 + off; outp = out + off;
        } else {
            int n = s - N1;
            size_t xoff = ((size_t)b * N1 + n) * Dd;
            size_t ioff = ((size_t)b * N2 + n) * Dd;
            xp = x2 + ioff; xop = g_xout + xoff; xo2p = g_xout2 + xoff; outp = out + GENE + ioff;
        }
        #pragma unroll
        for (int j = 0; j < 4; j++) {
            float lo, hi;
            unpack2(acc2[i][j], lo, hi);
            int c0 = nc + 32 * j;
            float o0 = lo + bsv[2 * j];
            float o1 = hi + bsv[2 * j + 1];
            float2 st;
            st.x = rw0 * lfp[c0]     + rw1 * (xop[c0]     + xo2p[c0])     + rw2 * o0 + rw3 * xp[c0];
            st.y = rw0 * lfp[c0 + 1] + rw1 * (xop[c0 + 1] + xo2p[c0 + 1]) + rw2 * o1 + rw3 * xp[c0 + 1];
            *(float2*)&outp[c0] = st;
        }
    }
}

// ---------------- attention v8: R11 compute, 64 q/block, K+V both resident ----
// 16 warps (512 thr), 4 q/warp, one fill of K AND V per block (no buffer swap).
// 213.5KB smem -> 1 CTA/SM (same 16 warps/SM as R11's 2x256, half the fills).
#define KTP 770

__global__ __launch_bounds__(512, 1) void attn_kernel(const float* __restrict__ qkv,
                                                      float* __restrict__ oattn) {
    extern __shared__ float smem[];
    float* Kt = smem;                     // 32 * 770 floats
    float* Vt = Kt + 32 * KTP;            // 32 * 770 floats
    ull* Qd = (ull*)(Vt + 32 * KTP);      // 16 warps * 128 ull, [d][i] layout
    int blk = blockIdx.x;
    int b = blk >> 3, h = blk & 7;
    int qc = blockIdx.y;                  // 0..11
    int tid = threadIdx.x, lane = tid & 31, w = tid >> 5;   // w: 0..15
    const float* base = qkv + (size_t)b * Ss * (3 * Dd);

    // ---- fill K and V transposed via float4 (one pass, both resident) ----
    for (int it = tid; it < Ss * 8; it += 512) {
        int j = it >> 3, c = it & 7;
        const float* row = base + (size_t)j * (3 * Dd) + h * HD + 4 * c;
        float4 vk = *(const float4*)(row + Dd);
        float4 vv = *(const float4*)(row + 2 * Dd);
        Kt[(4 * c + 0) * KTP + j] = vk.x;
        Kt[(4 * c + 1) * KTP + j] = vk.y;
        Kt[(4 * c + 2) * KTP + j] = vk.z;
        Kt[(4 * c + 3) * KTP + j] = vk.w;
        Vt[(4 * c + 0) * KTP + j] = vv.x;
        Vt[(4 * c + 1) * KTP + j] = vv.y;
        Vt[(4 * c + 2) * KTP + j] = vv.z;
        Vt[(4 * c + 3) * KTP + j] = vv.w;
    }

    // ---- stage this warp's 4 scaled queries, [d][i]-major packed ----
    const float scale = 0.17677669529663687f; // 1/sqrt(32)
    int qbase = qc * 64 + w * 4;
    ull* Qw = Qd + w * 128;
    #pragma unroll
    for (int i = 0; i < 4; i++) {
        float qv = base[(size_t)(qbase + i) * (3 * Dd) + h * HD + lane] * scale;
        Qw[lane * 4 + i] = pack2(qv, qv);
    }
    __syncthreads();

    // ---- QK^T: scores for key pair (64t + 2*lane, +1) ----
    ull s2[4][12];
    #pragma unroll
    for (int i = 0; i < 4; i++)
        #pragma unroll
        for (int t = 0; t < 12; t++) s2[i][t] = 0ull;

    #pragma unroll 2
    for (int d = 0; d < 32; d++) {
        ulonglong2 qa = *(const ulonglong2*)(Qw + d * 4);      // LDS.128 broadcast
        ulonglong2 qb = *(const ulonglong2*)(Qw + d * 4 + 2);
        const ull* kr = (const ull*)(Kt + d * KTP);
        #pragma unroll
        for (int t = 0; t < 12; t++) {
            ull k2 = kr[32 * t + lane];
            ffma2(s2[0][t], qa.x, k2);
            ffma2(s2[1][t], qa.y, k2);
            ffma2(s2[2][t], qb.x, k2);
            ffma2(s2[3][t], qb.y, k2);
        }
    }

    // ---- softmax, max-free (scores bounded far below exp overflow) ----
    #pragma unroll
    for (int i = 0; i < 4; i++) {
        float lo, hi;
        float sum = 0.f;
        #pragma unroll
        for (int t = 0; t < 12; t++) {
            unpack2(s2[i][t], lo, hi);
            lo = __expf(lo); hi = __expf(hi);
            sum += lo + hi;
            s2[i][t] = pack2(lo, hi);
        }
        #pragma unroll
        for (int o = 16; o; o >>= 1) sum += __shfl_xor_sync(0xffffffffu, sum, o);
        float iv = 1.f / sum;
        ull iv2 = pack2(iv, iv);
        #pragma unroll
        for (int t = 0; t < 12; t++) s2[i][t] = mul2(s2[i][t], iv2);
    }

    // ---- PV: per output dim, packed FMA + packed butterfly (V already resident) ----
    float o0 = 0.f, o1 = 0.f, o2 = 0.f, o3 = 0.f;
    for (int d = 0; d < 32; d++) {
        const ull* vr = (const ull*)(Vt + d * KTP);
        ull a0 = 0ull, a1 = 0ull, a2 = 0ull, a3 = 0ull;
        #pragma unroll
        for (int t = 0; t < 12; t++) {
            ull v2 = vr[32 * t + lane];
            ffma2(a0, s2[0][t], v2);
            ffma2(a1, s2[1][t], v2);
            ffma2(a2, s2[2][t], v2);
            ffma2(a3, s2[3][t], v2);
        }
        float lo, hi, r0, r1, r2, r3;
        unpack2(a0, lo, hi); r0 = lo + hi;
        unpack2(a1, lo, hi); r1 = lo + hi;
        unpack2(a2, lo, hi); r2 = lo + hi;
        unpack2(a3, lo, hi); r3 = lo + hi;
        ull p01 = pack2(r0, r1), p23 = pack2(r2, r3);
        #pragma unroll
        for (int os = 16; os; os >>= 1) {
            p01 = add2(p01, __shfl_xor_sync(0xffffffffu, p01, os));
            p23 = add2(p23, __shfl_xor_sync(0xffffffffu, p23, os));
        }
        if (lane == d) {
            unpack2(p01, o0, o1);
            unpack2(p23, o2, o3);
        }
    }
    oattn[((size_t)b * Ss + qbase + 0) * Dd + h * HD + lane] = o0;
    oattn[((size_t)b * Ss + qbase + 1) * Dd + h * HD + lane] = o1;
    oattn[((size_t)b * Ss + qbase + 2) * Dd + h * HD + lane] = o2;
    oattn[((size_t)b * Ss + qbase + 3) * Dd + h * HD + lane] = o3;
}

// ---------------- launch ----------------
extern "C" void kernel_launch(void* const* d_in, const int* in_sizes, int n_in,
                              void* d_out, int out_size) {
    const float* x1        = (const float*)d_in[0];
    const float* x2        = (const float*)d_in[1];
    const float* r_w1      = (const float*)d_in[2];
    const float* r_b1      = (const float*)d_in[3];
    const float* ln_g      = (const float*)d_in[4];
    const float* ln_b      = (const float*)d_in[5];
    const float* r_w2      = (const float*)d_in[6];
    const float* r_b2      = (const float*)d_in[7];
    const float* lf_w      = (const float*)d_in[8];
    const float* lf_b      = (const float*)d_in[9];
    const float* af2_w     = (const float*)d_in[10];
    const float* af2_b     = (const float*)d_in[11];
    const float* af3_w     = (const float*)d_in[12];
    const float* af3_b     = (const float*)d_in[13];
    const float* attn_in_w = (const float*)d_in[14];
    const float* attn_in_b = (const float*)d_in[15];
    const float* attn_out_w= (const float*)d_in[16];
    const float* attn_out_b= (const float*)d_in[17];
    float* out = (float*)d_out;

    float *p_lf, *p_xout, *p_xout2, *p_qkv, *p_oattn;
    cudaGetSymbolAddress((void**)&p_lf, g_lf);
    cudaGetSymbolAddress((void**)&p_xout, g_xout);
    cudaGetSymbolAddress((void**)&p_xout2, g_xout2);
    cudaGetSymbolAddress((void**)&p_qkv, g_qkv);
    cudaGetSymbolAddress((void**)&p_oattn, g_oattn);

    const int ATTN_SMEM = (2 * 32 * KTP) * 4 + 16 * 128 * 8; // 197120 + 16384 = 213504 B
    cudaFuncSetAttribute(attn_kernel, cudaFuncAttributeMaxDynamicSharedMemorySize, ATTN_SMEM);

    // means + router
    mean_kernel<<<dim3(Bsz, 2), 256>>>(x1, x2);
    router_kernel<<<Bsz, 256>>>(r_w1, r_b1, ln_g, ln_b, r_w2, r_b2);
    // fused: lf, af2, qkv, af3 (2048 blocks, one tail)
    mega_gemm<<<2048, 256>>>(x1, x2, lf_w, lf_b, af2_w, af2_b, af3_w, af3_b,
                             attn_in_w, attn_in_b, p_lf, p_xout, p_xout2, p_qkv);
    // attention (64 q/block, K+V resident, one fill)
    attn_kernel<<<dim3(Bsz * Hh, 12), 512, ATTN_SMEM>>>(p_qkv, p_oattn);
    // attn_out projection with fused router combine -> writes final output
    gemm_out_combine<<<dim3(Dd / BN, (Bsz * Ss) / BM), 256>>>(p_oattn, attn_out_w, attn_out_b,
                                                              x1, x2, out);
}